// round 1
// baseline (speedup 1.0000x reference)
#include <cuda_runtime.h>
#include <math.h>

#define BATCH 16384
#define NEXP  5

// ---------------- scratch (static device globals; no allocation) ------------
__device__ float d_bufA[BATCH * 256];   // INet ping  (i1, then ienc)
__device__ float d_bufB[BATCH * 256];   // INet pong  (i2), then g1
__device__ float d_h0  [BATCH * 812];   // [z | p_prev | ienc]
__device__ float d_g2  [BATCH * 128];
__device__ float d_omega[BATCH * NEXP];
__device__ float d_h1  [BATCH * 256];
__device__ float d_c2  [BATCH * 288];   // [z | h1]
__device__ float d_h2  [BATCH * 256];
__device__ float d_c3  [BATCH * 288];   // [z | h2]

// ---------------- generic tiled GEMM --------------------------------------
// C[M,N] = act( A'[M,K] @ W[K,N] + bias ),  M = BATCH fixed multiple of 128.
// MODE 0: A'[m,k] = A[m*lda + k]                      bias[n]
// MODE 1: A'[m,k] = omega[m,e] * A[m*lda + i],        e=k/INDIM, i=k%INDIM
//                   bias contribution = sum_e omega[m,e]*bias[e*N+n]
// Tile: 128x64x16, 256 threads, 8x4 microtile per thread.
template <int MODE, bool DO_ELU, int INDIM>
__global__ __launch_bounds__(256)
void gemm_k(const float* __restrict__ A, int lda,
            const float* __restrict__ omega,
            const float* __restrict__ W,
            const float* __restrict__ bias,
            float* __restrict__ C, int ldc,
            int N, int K)
{
    __shared__ float As[16][132];   // [k][m], padded
    __shared__ float Bs[16][64];    // [k][n]

    const int tid = threadIdx.x;
    const int bm  = blockIdx.y * 128;
    const int bn  = blockIdx.x * 64;
    const int tx  = tid & 15;       // 4 cols each
    const int ty  = tid >> 4;       // 8 rows each
    const int lk  = tid & 15;       // A-load k within tile
    const int lm0 = tid >> 4;       // A-load row base
    const int bn0 = tid & 63;       // B-load n
    const int bk0 = tid >> 6;       // B-load k base

    float acc[8][4];
#pragma unroll
    for (int i = 0; i < 8; i++)
#pragma unroll
        for (int j = 0; j < 4; j++) acc[i][j] = 0.f;

    for (int kb = 0; kb < K; kb += 16) {
        const int gk = kb + lk;
#pragma unroll
        for (int r = 0; r < 8; r++) {
            const int m  = lm0 + r * 16;
            const int gm = bm + m;
            float v = 0.f;
            if (gk < K) {
                if (MODE == 0) {
                    v = A[gm * lda + gk];
                } else {
                    const int e = gk / INDIM;          // compile-time INDIM
                    const int i = gk - e * INDIM;
                    v = omega[gm * NEXP + e] * A[gm * lda + i];
                }
            }
            As[lk][m] = v;
        }
#pragma unroll
        for (int r = 0; r < 4; r++) {
            const int kk  = bk0 + r * 4;
            const int gk2 = kb + kk;
            const int gn  = bn + bn0;
            float v = 0.f;
            if (gk2 < K && gn < N) v = W[gk2 * N + gn];
            Bs[kk][bn0] = v;
        }
        __syncthreads();

#pragma unroll
        for (int k = 0; k < 16; k++) {
            float a[8], b[4];
#pragma unroll
            for (int i = 0; i < 8; i++) a[i] = As[k][ty * 8 + i];
#pragma unroll
            for (int j = 0; j < 4; j++) b[j] = Bs[k][tx * 4 + j];
#pragma unroll
            for (int i = 0; i < 8; i++)
#pragma unroll
                for (int j = 0; j < 4; j++)
                    acc[i][j] = fmaf(a[i], b[j], acc[i][j]);
        }
        __syncthreads();
    }

#pragma unroll
    for (int i = 0; i < 8; i++) {
        const int gm = bm + ty * 8 + i;
        float om[NEXP];
        if (MODE == 1) {
#pragma unroll
            for (int e = 0; e < NEXP; e++) om[e] = omega[gm * NEXP + e];
        }
#pragma unroll
        for (int j = 0; j < 4; j++) {
            const int gn = bn + tx * 4 + j;
            if (gn < N) {
                float v = acc[i][j];
                if (MODE == 0) {
                    v += bias[gn];
                } else {
#pragma unroll
                    for (int e = 0; e < NEXP; e++)
                        v = fmaf(om[e], bias[e * N + gn], v);
                }
                if (DO_ELU) v = (v > 0.f) ? v : expm1f(v);
                C[gm * ldc + gn] = v;
            }
        }
    }
}

// ---------------- gating layer 3 + softmax (one warp per row) ---------------
__global__ void gate3_softmax_k(const float* __restrict__ g2,
                                const float* __restrict__ gw3,
                                const float* __restrict__ gb3,
                                float* __restrict__ omega)
{
    const int warp = (blockIdx.x * blockDim.x + threadIdx.x) >> 5;
    const int lane = threadIdx.x & 31;
    if (warp >= BATCH) return;
    const float* row = g2 + warp * 128;
    float p[NEXP] = {0.f, 0.f, 0.f, 0.f, 0.f};
#pragma unroll
    for (int r = 0; r < 4; r++) {
        const int k = lane + r * 32;
        const float x = row[k];
#pragma unroll
        for (int e = 0; e < NEXP; e++)
            p[e] = fmaf(x, gw3[k * NEXP + e], p[e]);
    }
#pragma unroll
    for (int e = 0; e < NEXP; e++) {
#pragma unroll
        for (int off = 16; off > 0; off >>= 1)
            p[e] += __shfl_xor_sync(0xffffffffu, p[e], off);
    }
    if (lane == 0) {
        float mx = -1e30f;
#pragma unroll
        for (int e = 0; e < NEXP; e++) { p[e] += gb3[e]; mx = fmaxf(mx, p[e]); }
        float s = 0.f;
#pragma unroll
        for (int e = 0; e < NEXP; e++) { p[e] = expf(p[e] - mx); s += p[e]; }
        const float inv = 1.f / s;
#pragma unroll
        for (int e = 0; e < NEXP; e++) omega[warp * NEXP + e] = p[e] * inv;
    }
}

// ---------------- concats ---------------------------------------------------
__global__ void concat_h0_k(const float* __restrict__ z,
                            const float* __restrict__ p,
                            const float* __restrict__ ienc,
                            float* __restrict__ h0)
{
    const int idx = blockIdx.x * blockDim.x + threadIdx.x;
    if (idx >= BATCH * 812) return;
    const int b = idx / 812, c = idx - b * 812;
    float v;
    if (c < 32)       v = z[b * 32 + c];
    else if (c < 556) v = p[b * 524 + (c - 32)];
    else              v = ienc[b * 256 + (c - 556)];
    h0[idx] = v;
}

__global__ void concat_z_k(const float* __restrict__ z,
                           const float* __restrict__ h,
                           float* __restrict__ out)
{
    const int idx = blockIdx.x * blockDim.x + threadIdx.x;
    if (idx >= BATCH * 288) return;
    const int b = idx / 288, c = idx - b * 288;
    out[idx] = (c < 32) ? z[b * 32 + c] : h[b * 256 + (c - 32)];
}

// ---------------- launcher --------------------------------------------------
extern "C" void kernel_launch(void* const* d_in, const int* in_sizes, int n_in,
                              void* d_out, int out_size)
{
    const float* z      = (const float*)d_in[0];
    const float* p_prev = (const float*)d_in[1];
    const float* I      = (const float*)d_in[2];
    const float* gw1 = (const float*)d_in[3];  const float* gb1 = (const float*)d_in[4];
    const float* gw2 = (const float*)d_in[5];  const float* gb2 = (const float*)d_in[6];
    const float* gw3 = (const float*)d_in[7];  const float* gb3 = (const float*)d_in[8];
    const float* iw1 = (const float*)d_in[9];  const float* ib1 = (const float*)d_in[10];
    const float* iw2 = (const float*)d_in[11]; const float* ib2 = (const float*)d_in[12];
    const float* iw3 = (const float*)d_in[13]; const float* ib3 = (const float*)d_in[14];
    const float* wl1 = (const float*)d_in[15]; const float* bl1 = (const float*)d_in[16];
    const float* wl2 = (const float*)d_in[17]; const float* bl2 = (const float*)d_in[18];
    const float* wl3 = (const float*)d_in[19]; const float* bl3 = (const float*)d_in[20];
    float* out = (float*)d_out;

    float *bufA, *bufB, *h0, *g2, *omega, *h1, *c2, *h2, *c3;
    cudaGetSymbolAddress((void**)&bufA,  d_bufA);
    cudaGetSymbolAddress((void**)&bufB,  d_bufB);
    cudaGetSymbolAddress((void**)&h0,    d_h0);
    cudaGetSymbolAddress((void**)&g2,    d_g2);
    cudaGetSymbolAddress((void**)&omega, d_omega);
    cudaGetSymbolAddress((void**)&h1,    d_h1);
    cudaGetSymbolAddress((void**)&c2,    d_c2);
    cudaGetSymbolAddress((void**)&h2,    d_h2);
    cudaGetSymbolAddress((void**)&c3,    d_c3);

    const dim3 blk(256);
    const dim3 g256(256 / 64, BATCH / 128);   // N=256
    const dim3 g128(128 / 64, BATCH / 128);   // N=128
    const dim3 g524((524 + 63) / 64, BATCH / 128);

    // INet: 2048 -> 256 -> 256 -> 256 (ELU each)
    gemm_k<0, true, 1><<<g256, blk>>>(I,    2048, nullptr, iw1, ib1, bufA, 256, 256, 2048);
    gemm_k<0, true, 1><<<g256, blk>>>(bufA,  256, nullptr, iw2, ib2, bufB, 256, 256,  256);
    gemm_k<0, true, 1><<<g256, blk>>>(bufB,  256, nullptr, iw3, ib3, bufA, 256, 256,  256);

    // h0 = [z | p_prev | ienc]   (ienc in bufA)
    concat_h0_k<<<(BATCH * 812 + 255) / 256, blk>>>(z, p_prev, bufA, h0);

    // gating: uses h0[:, :556] = [z | p_prev]
    gemm_k<0, true, 1><<<g256, blk>>>(h0,   812, nullptr, gw1, gb1, bufB, 256, 256, 556);
    gemm_k<0, true, 1><<<g128, blk>>>(bufB, 256, nullptr, gw2, gb2, g2,   128, 128, 256);
    gate3_softmax_k<<<BATCH / 8, blk>>>(g2, gw3, gb3, omega);

    // MoE layer 1: K = 5*812 = 4060, omega-scaled A loader
    gemm_k<1, true, 812><<<g256, blk>>>(h0, 812, omega, wl1, bl1, h1, 256, 256, 4060);

    // layer 2: input [z | h1], K = 5*288 = 1440
    concat_z_k<<<(BATCH * 288 + 255) / 256, blk>>>(z, h1, c2);
    gemm_k<1, true, 288><<<g256, blk>>>(c2, 288, omega, wl2, bl2, h2, 256, 256, 1440);

    // layer 3: input [z | h2], K = 1440, N = 524, no ELU
    concat_z_k<<<(BATCH * 288 + 255) / 256, blk>>>(z, h2, c3);
    gemm_k<1, false, 288><<<g524, blk>>>(c3, 288, omega, wl3, bl3, out, 524, 524, 1440);
}

// round 3
// speedup vs baseline: 1.1351x; 1.1351x over previous
#include <cuda_runtime.h>
#include <math.h>
#include <cstdint>

#define BATCH 16384
#define NEXP  5

// ---------------- scratch (static device globals; no allocation) ------------
__device__ float d_bufA [BATCH * 256];
__device__ float d_bufB [BATCH * 256];
__device__ float d_g2   [BATCH * 128];
__device__ float d_omega[BATCH * NEXP];
__device__ float d_h1   [BATCH * 256];
__device__ float d_h2   [BATCH * 256];

// ---------------- helpers ----------------------------------------------------
__device__ __forceinline__ uint32_t f2tf(float v) {
    uint32_t r;
    asm("cvt.rna.tf32.f32 %0, %1;" : "=r"(r) : "f"(v));
    return r;
}

__device__ __forceinline__ void mma8(float* d, const uint32_t* a, const uint32_t* b) {
    asm volatile(
        "mma.sync.aligned.m16n8k8.row.col.f32.tf32.tf32.f32 "
        "{%0,%1,%2,%3}, {%4,%5,%6,%7}, {%8,%9}, {%0,%1,%2,%3};"
        : "+f"(d[0]), "+f"(d[1]), "+f"(d[2]), "+f"(d[3])
        : "r"(a[0]), "r"(a[1]), "r"(a[2]), "r"(a[3]), "r"(b[0]), "r"(b[1]));
}

// ---------------- tensor-core GEMM (mma.sync, tf32) --------------------------
// C[M,N] = act(A'[M,K] @ W[K,N] + bias').  Block 128x128x32, warp 64x32.
// CONCAT 0: A' = A[m*lda + k]
// CONCAT 1: cols (z:32 | p_prev:524 | ienc:256), optional omega scale
// CONCAT 2: cols (z:32 | h:256),               optional omega scale
template <int CONCAT, bool SCALED, bool DO_ELU, int INDIM>
__global__ __launch_bounds__(256, 1)
void mma_gemm(const float* __restrict__ A, int lda,
              const float* __restrict__ S1, const float* __restrict__ S2,
              const float* __restrict__ S3,
              const float* __restrict__ omega,
              const float* __restrict__ W, const float* __restrict__ bias,
              float* __restrict__ C, int ldc, int N, int K)
{
    __shared__ uint32_t As[128 * 36];   // [m][k], stride 36 (frag loads conflict-free)
    __shared__ uint32_t Bs[32 * 132];   // [k][n], stride 132

    const int tid    = threadIdx.x;
    const int wid    = tid >> 5;
    const int lane   = tid & 31;
    const int warp_m = wid & 1;         // 2 warp rows x 64
    const int warp_n = wid >> 1;        // 4 warp cols x 32
    const int bm     = blockIdx.y * 128;
    const int n0     = blockIdx.x * 128;
    const int r0     = lane >> 2;       // 0..7
    const int c0     = lane & 3;        // 0..3

    float d[4][4][4];
#pragma unroll
    for (int mt = 0; mt < 4; mt++)
#pragma unroll
        for (int nt = 0; nt < 4; nt++)
#pragma unroll
            for (int r = 0; r < 4; r++) d[mt][nt][r] = 0.f;

    const int NC = (K + 31) / 32;

    float4 aS4[4];    // CONCAT0 staging
    float  aS[16];    // CONCAT1/2 staging
    float  bS[16];

    auto loadA = [&](int c) {
        const int kb = c * 32;
        if (CONCAT == 0) {
#pragma unroll
            for (int t = 0; t < 4; t++) {
                const int idx = tid + t * 256;          // 1024 float4
                const int row = idx >> 3, k4 = idx & 7;
                aS4[t] = *(const float4*)(A + (size_t)(bm + row) * lda + kb + k4 * 4);
            }
        } else {
#pragma unroll
            for (int t = 0; t < 16; t++) {
                const int idx = tid + t * 256;          // 4096 floats
                const int row = idx >> 5, k = idx & 31;
                const int gk = kb + k, gm = bm + row;
                float v = 0.f;
                if (gk < K) {
                    int e = 0, i = gk;
                    if (SCALED) { e = gk / INDIM; i = gk - e * INDIM; }
                    if (CONCAT == 1) {
                        if (i < 32)       v = S1[gm * 32 + i];
                        else if (i < 556) v = S2[gm * 524 + (i - 32)];
                        else              v = S3[gm * 256 + (i - 556)];
                    } else {
                        v = (i < 32) ? S1[gm * 32 + i] : S2[gm * 256 + (i - 32)];
                    }
                    if (SCALED) v *= omega[gm * NEXP + e];
                }
                aS[t] = v;
            }
        }
    };
    auto loadB = [&](int c) {
        const int kb = c * 32;
#pragma unroll
        for (int t = 0; t < 16; t++) {
            const int idx = tid + t * 256;              // 4096 floats
            const int n = idx & 127, k = idx >> 7;
            const int gk = kb + k, gn = n0 + n;
            bS[t] = (gk < K && gn < N) ? W[(size_t)gk * N + gn] : 0.f;
        }
    };
    auto storeA = [&]() {
        if (CONCAT == 0) {
#pragma unroll
            for (int t = 0; t < 4; t++) {
                const int idx = tid + t * 256;
                const int row = idx >> 3, k4 = idx & 7;
                uint32_t* p = &As[row * 36 + k4 * 4];
                p[0] = f2tf(aS4[t].x); p[1] = f2tf(aS4[t].y);
                p[2] = f2tf(aS4[t].z); p[3] = f2tf(aS4[t].w);
            }
        } else {
#pragma unroll
            for (int t = 0; t < 16; t++) {
                const int idx = tid + t * 256;
                const int row = idx >> 5, k = idx & 31;
                As[row * 36 + k] = f2tf(aS[t]);
            }
        }
    };
    auto storeB = [&]() {
#pragma unroll
        for (int t = 0; t < 16; t++) {
            const int idx = tid + t * 256;
            const int n = idx & 127, k = idx >> 7;
            Bs[k * 132 + n] = f2tf(bS[t]);
        }
    };
    auto compute = [&]() {
#pragma unroll
        for (int ks = 0; ks < 4; ks++) {
            uint32_t a[4][4], b[4][2];
            const int col = ks * 8 + c0;
#pragma unroll
            for (int mt = 0; mt < 4; mt++) {
                const int base = warp_m * 64 + mt * 16;
                a[mt][0] = As[(base + r0)     * 36 + col];
                a[mt][1] = As[(base + r0 + 8) * 36 + col];
                a[mt][2] = As[(base + r0)     * 36 + col + 4];
                a[mt][3] = As[(base + r0 + 8) * 36 + col + 4];
            }
            const int kk = ks * 8 + c0;
#pragma unroll
            for (int nt = 0; nt < 4; nt++) {
                const int n = warp_n * 32 + nt * 8 + r0;
                b[nt][0] = Bs[kk       * 132 + n];
                b[nt][1] = Bs[(kk + 4) * 132 + n];
            }
#pragma unroll
            for (int mt = 0; mt < 4; mt++)
#pragma unroll
                for (int nt = 0; nt < 4; nt++)
                    mma8(d[mt][nt], a[mt], b[nt]);
        }
    };

    // pipeline: regs hold next tile while smem feeds current MMAs
    loadA(0); loadB(0);
    storeA(); storeB();
    __syncthreads();
    for (int c = 0; c < NC; c++) {
        if (c + 1 < NC) { loadA(c + 1); loadB(c + 1); }
        compute();
        __syncthreads();
        if (c + 1 < NC) { storeA(); storeB(); __syncthreads(); }
    }

    // ---- epilogue: bias (plain or omega-blended) + ELU, float2 stores ----
#pragma unroll
    for (int mt = 0; mt < 4; mt++) {
#pragma unroll
        for (int half = 0; half < 2; half++) {
            const int gm = bm + warp_m * 64 + mt * 16 + r0 + half * 8;
            float om[NEXP];
            if (SCALED) {
#pragma unroll
                for (int e = 0; e < NEXP; e++) om[e] = omega[gm * NEXP + e];
            }
#pragma unroll
            for (int nt = 0; nt < 4; nt++) {
                const int gn = n0 + warp_n * 32 + nt * 8 + c0 * 2;
                if (gn < N) {
                    float v0 = d[mt][nt][half * 2 + 0];
                    float v1 = d[mt][nt][half * 2 + 1];
                    if (SCALED) {
#pragma unroll
                        for (int e = 0; e < NEXP; e++) {
                            v0 = fmaf(om[e], bias[e * N + gn],     v0);
                            v1 = fmaf(om[e], bias[e * N + gn + 1], v1);
                        }
                    } else {
                        v0 += bias[gn];
                        v1 += bias[gn + 1];
                    }
                    if (DO_ELU) {
                        v0 = (v0 > 0.f) ? v0 : expm1f(v0);
                        v1 = (v1 > 0.f) ? v1 : expm1f(v1);
                    }
                    *(float2*)(C + (size_t)gm * ldc + gn) = make_float2(v0, v1);
                }
            }
        }
    }
}

// ---------------- gating layer 3 + softmax ----------------------------------
__global__ void gate3_softmax_k(const float* __restrict__ g2,
                                const float* __restrict__ gw3,
                                const float* __restrict__ gb3,
                                float* __restrict__ omega)
{
    const int warp = (blockIdx.x * blockDim.x + threadIdx.x) >> 5;
    const int lane = threadIdx.x & 31;
    if (warp >= BATCH) return;
    const float* row = g2 + warp * 128;
    float p[NEXP] = {0.f, 0.f, 0.f, 0.f, 0.f};
#pragma unroll
    for (int r = 0; r < 4; r++) {
        const int k = lane + r * 32;
        const float x = row[k];
#pragma unroll
        for (int e = 0; e < NEXP; e++) p[e] = fmaf(x, gw3[k * NEXP + e], p[e]);
    }
#pragma unroll
    for (int e = 0; e < NEXP; e++)
#pragma unroll
        for (int off = 16; off > 0; off >>= 1)
            p[e] += __shfl_xor_sync(0xffffffffu, p[e], off);
    if (lane == 0) {
        float mx = -1e30f;
#pragma unroll
        for (int e = 0; e < NEXP; e++) { p[e] += gb3[e]; mx = fmaxf(mx, p[e]); }
        float s = 0.f;
#pragma unroll
        for (int e = 0; e < NEXP; e++) { p[e] = expf(p[e] - mx); s += p[e]; }
        const float inv = 1.f / s;
#pragma unroll
        for (int e = 0; e < NEXP; e++) omega[warp * NEXP + e] = p[e] * inv;
    }
}

// ---------------- launcher ----------------------------------------------------
extern "C" void kernel_launch(void* const* d_in, const int* in_sizes, int n_in,
                              void* d_out, int out_size)
{
    const float* z      = (const float*)d_in[0];
    const float* p_prev = (const float*)d_in[1];
    const float* I      = (const float*)d_in[2];
    const float* gw1 = (const float*)d_in[3];  const float* gb1 = (const float*)d_in[4];
    const float* gw2 = (const float*)d_in[5];  const float* gb2 = (const float*)d_in[6];
    const float* gw3 = (const float*)d_in[7];  const float* gb3 = (const float*)d_in[8];
    const float* iw1 = (const float*)d_in[9];  const float* ib1 = (const float*)d_in[10];
    const float* iw2 = (const float*)d_in[11]; const float* ib2 = (const float*)d_in[12];
    const float* iw3 = (const float*)d_in[13]; const float* ib3 = (const float*)d_in[14];
    const float* wl1 = (const float*)d_in[15]; const float* bl1 = (const float*)d_in[16];
    const float* wl2 = (const float*)d_in[17]; const float* bl2 = (const float*)d_in[18];
    const float* wl3 = (const float*)d_in[19]; const float* bl3 = (const float*)d_in[20];
    float* out = (float*)d_out;

    float *bufA, *bufB, *g2, *omega, *h1, *h2;
    cudaGetSymbolAddress((void**)&bufA,  d_bufA);
    cudaGetSymbolAddress((void**)&bufB,  d_bufB);
    cudaGetSymbolAddress((void**)&g2,    d_g2);
    cudaGetSymbolAddress((void**)&omega, d_omega);
    cudaGetSymbolAddress((void**)&h1,    d_h1);
    cudaGetSymbolAddress((void**)&h2,    d_h2);

    const dim3 blk(256);
    const dim3 gN256(2, BATCH / 128);
    const dim3 gN128(1, BATCH / 128);
    const dim3 gN524(5, BATCH / 128);

    // INet: 2048 -> 256 -> 256 -> 256 (ELU)
    mma_gemm<0, false, true, 1><<<gN256, blk>>>(I,    2048, nullptr, nullptr, nullptr, nullptr, iw1, ib1, bufA, 256, 256, 2048);
    mma_gemm<0, false, true, 1><<<gN256, blk>>>(bufA,  256, nullptr, nullptr, nullptr, nullptr, iw2, ib2, bufB, 256, 256,  256);
    mma_gemm<0, false, true, 1><<<gN256, blk>>>(bufB,  256, nullptr, nullptr, nullptr, nullptr, iw3, ib3, bufA, 256, 256,  256);

    // gating: [z | p_prev] -> 256 -> 128 -> softmax(5)
    mma_gemm<1, false, true, 1><<<gN256, blk>>>(nullptr, 0, z, p_prev, nullptr, nullptr, gw1, gb1, bufB, 256, 256, 556);
    mma_gemm<0, false, true, 1><<<gN128, blk>>>(bufB, 256, nullptr, nullptr, nullptr, nullptr, gw2, gb2, g2, 128, 128, 256);
    gate3_softmax_k<<<BATCH / 8, blk>>>(g2, gw3, gb3, omega);

    // MoE layers (omega-scaled concat A, flat-K GEMM); ienc lives in bufA
    mma_gemm<1, true, true,  812><<<gN256, blk>>>(nullptr, 0, z, p_prev, bufA, omega, wl1, bl1, h1, 256, 256, 4060);
    mma_gemm<2, true, true,  288><<<gN256, blk>>>(nullptr, 0, z, h1, nullptr, omega, wl2, bl2, h2, 256, 256, 1440);
    mma_gemm<2, true, false, 288><<<gN524, blk>>>(nullptr, 0, z, h2, nullptr, omega, wl3, bl3, out, 524, 524, 1440);
}

// round 4
// speedup vs baseline: 3.1587x; 2.7827x over previous
#include <cuda_runtime.h>
#include <math.h>
#include <cstdint>

#define BATCH 16384
#define NEXP  5

// ---------------- scratch (static device globals; no allocation) ------------
__device__ float d_bufA [BATCH * 256];
__device__ float d_bufB [BATCH * 256];
__device__ float d_g2   [BATCH * 128];
__device__ float d_omega[BATCH * NEXP];
__device__ float d_h1   [BATCH * 256];
__device__ float d_h2   [BATCH * 256];
__device__ float d_a1   [(size_t)BATCH * 4060];  // moe1 scaled-concat A'
__device__ float d_a23  [(size_t)BATCH * 1440];  // moe2/3 scaled-concat A' (reused)

// ---------------- helpers ----------------------------------------------------
__device__ __forceinline__ uint32_t f2tf(float v) {
    uint32_t r;
    asm("cvt.rna.tf32.f32 %0, %1;" : "=r"(r) : "f"(v));
    return r;
}
__device__ __forceinline__ void mma8(float* d, const uint32_t* a, const uint32_t* b) {
    asm volatile(
        "mma.sync.aligned.m16n8k8.row.col.f32.tf32.tf32.f32 "
        "{%0,%1,%2,%3}, {%4,%5,%6,%7}, {%8,%9}, {%0,%1,%2,%3};"
        : "+f"(d[0]), "+f"(d[1]), "+f"(d[2]), "+f"(d[3])
        : "r"(a[0]), "r"(a[1]), "r"(a[2]), "r"(a[3]), "r"(b[0]), "r"(b[1]));
}
__device__ __forceinline__ void cp8(uint32_t dst, const void* src, bool ok) {
    asm volatile("cp.async.ca.shared.global [%0], [%1], 8, %2;"
                 :: "r"(dst), "l"(src), "r"(ok ? 8 : 0) : "memory");
}
__device__ __forceinline__ void cp_commit() {
    asm volatile("cp.async.commit_group;" ::: "memory");
}
template <int NPEND> __device__ __forceinline__ void cp_wait() {
    asm volatile("cp.async.wait_group %0;" :: "n"(NPEND) : "memory");
}

// ---------------- tensor-core GEMM (cp.async double-buffered) ----------------
// C[M,N] = act(A'[M,K] @ W[K,N] + bias').  Block 128x128x32, warp 64x32.
// CONCAT 0: A' = A[m*lda + k]      (raw fp32; cvt to tf32 at fragment load)
// CONCAT 1: A' = cols (z:32 | p_prev:524)  -- address-computed cp.async gather
// SCALED: epilogue bias = sum_e omega[m,e]*bias[e*N+n], else bias[n]
template <int CONCAT, bool SCALED, bool DO_ELU>
__global__ __launch_bounds__(256, 2)
void mma_gemm(const float* __restrict__ A, int lda,
              const float* __restrict__ S1, const float* __restrict__ S2,
              const float* __restrict__ omega,
              const float* __restrict__ W, const float* __restrict__ bias,
              float* __restrict__ C, int ldc, int N, int K)
{
    extern __shared__ float smem[];
    float* As = smem;               // 2 x 128 x 36
    float* Bs = smem + 2 * 4608;    // 2 x 32 x 132

    const int tid    = threadIdx.x;
    const int wid    = tid >> 5;
    const int lane   = tid & 31;
    const int warp_m = wid & 1;
    const int warp_n = wid >> 1;
    const int bm     = blockIdx.y * 128;
    const int n0     = blockIdx.x * 128;
    const int r0     = lane >> 2;
    const int c0     = lane & 3;

    const uint32_t sA = (uint32_t)__cvta_generic_to_shared(As);
    const uint32_t sB = (uint32_t)__cvta_generic_to_shared(Bs);

    float d[4][4][4];
#pragma unroll
    for (int mt = 0; mt < 4; mt++)
#pragma unroll
        for (int nt = 0; nt < 4; nt++)
#pragma unroll
            for (int r = 0; r < 4; r++) d[mt][nt][r] = 0.f;

    const int NC = (K + 31) / 32;

    auto issue = [&](int c) {
        const int kb  = c * 32;
        const int buf = c & 1;
        // A tile: 128 rows x 32 k, 8B chunks, 8 per thread
#pragma unroll
        for (int t = 0; t < 8; t++) {
            const int idx = tid + t * 256;
            const int row = idx >> 4;
            const int kp  = (idx & 15) * 2;
            const int gk  = kb + kp;
            const int gm  = bm + row;
            const uint32_t dst = sA + ((buf * 4608 + row * 36 + kp) << 2);
            const float* src;
            if (CONCAT == 0) src = A + (size_t)gm * lda + gk;
            else src = (gk < 32) ? (S1 + gm * 32 + gk) : (S2 + gm * 524 + (gk - 32));
            cp8(dst, src, gk < K);
        }
        // B tile: 32 k x 128 n, 8B chunks, 8 per thread
#pragma unroll
        for (int t = 0; t < 8; t++) {
            const int idx = tid + t * 256;
            const int k   = idx >> 6;
            const int np  = (idx & 63) * 2;
            const int gk  = kb + k;
            const int gn  = n0 + np;
            const uint32_t dst = sB + ((buf * 4224 + k * 132 + np) << 2);
            cp8(dst, W + (size_t)gk * N + gn, (gk < K) && (gn < N));
        }
        cp_commit();
    };

    auto compute = [&](int buf) {
        const float* Ab = As + buf * 4608;
        const float* Bb = Bs + buf * 4224;
#pragma unroll
        for (int ks = 0; ks < 4; ks++) {
            uint32_t a[4][4], b[4][2];
            const int col = ks * 8 + c0;
#pragma unroll
            for (int mt = 0; mt < 4; mt++) {
                const int base = warp_m * 64 + mt * 16;
                a[mt][0] = f2tf(Ab[(base + r0)     * 36 + col]);
                a[mt][1] = f2tf(Ab[(base + r0 + 8) * 36 + col]);
                a[mt][2] = f2tf(Ab[(base + r0)     * 36 + col + 4]);
                a[mt][3] = f2tf(Ab[(base + r0 + 8) * 36 + col + 4]);
            }
#pragma unroll
            for (int nt = 0; nt < 4; nt++) {
                const int n = warp_n * 32 + nt * 8 + r0;
                b[nt][0] = f2tf(Bb[col       * 132 + n]);
                b[nt][1] = f2tf(Bb[(col + 4) * 132 + n]);
            }
#pragma unroll
            for (int mt = 0; mt < 4; mt++)
#pragma unroll
                for (int nt = 0; nt < 4; nt++)
                    mma8(d[mt][nt], a[mt], b[nt]);
        }
    };

    issue(0);
    for (int c = 0; c < NC; c++) {
        if (c + 1 < NC) { issue(c + 1); cp_wait<1>(); }
        else            { cp_wait<0>(); }
        __syncthreads();
        compute(c & 1);
        __syncthreads();
    }

    // ---- epilogue: bias (plain or omega-blended) + ELU, float2 stores -------
#pragma unroll
    for (int mt = 0; mt < 4; mt++) {
#pragma unroll
        for (int half = 0; half < 2; half++) {
            const int gm = bm + warp_m * 64 + mt * 16 + r0 + half * 8;
            float om[NEXP];
            if (SCALED) {
#pragma unroll
                for (int e = 0; e < NEXP; e++) om[e] = omega[gm * NEXP + e];
            }
#pragma unroll
            for (int nt = 0; nt < 4; nt++) {
                const int gn = n0 + warp_n * 32 + nt * 8 + c0 * 2;
                if (gn < N) {
                    float v0 = d[mt][nt][half * 2 + 0];
                    float v1 = d[mt][nt][half * 2 + 1];
                    if (SCALED) {
#pragma unroll
                        for (int e = 0; e < NEXP; e++) {
                            v0 = fmaf(om[e], bias[e * N + gn],     v0);
                            v1 = fmaf(om[e], bias[e * N + gn + 1], v1);
                        }
                    } else {
                        v0 += bias[gn];
                        v1 += bias[gn + 1];
                    }
                    if (DO_ELU) {
                        v0 = (v0 > 0.f) ? v0 : expm1f(v0);
                        v1 = (v1 > 0.f) ? v1 : expm1f(v1);
                    }
                    *(float2*)(C + (size_t)gm * ldc + gn) = make_float2(v0, v1);
                }
            }
        }
    }
}

// ---------------- A' materialization (omega-scaled concat) -------------------
__global__ void prep_moe1_k(const float* __restrict__ z,
                            const float* __restrict__ p,
                            const float* __restrict__ ienc,
                            const float* __restrict__ omega,
                            float* __restrict__ out)
{
    const int NC4 = 4060 / 4;  // 1015
    const int idx = blockIdx.x * blockDim.x + threadIdx.x;
    if (idx >= BATCH * NC4) return;
    const int m   = idx / NC4;
    const int col = (idx - m * NC4) * 4;
    const int e   = col / 812;
    const int i   = col - e * 812;
    float4 v;
    if (i < 32)       v = *(const float4*)(z    + m * 32  + i);
    else if (i < 556) v = *(const float4*)(p    + m * 524 + (i - 32));
    else              v = *(const float4*)(ienc + m * 256 + (i - 556));
    const float w = omega[m * NEXP + e];
    v.x *= w; v.y *= w; v.z *= w; v.w *= w;
    *(float4*)(out + (size_t)m * 4060 + col) = v;
}

__global__ void prep_moe23_k(const float* __restrict__ z,
                             const float* __restrict__ h,
                             const float* __restrict__ omega,
                             float* __restrict__ out)
{
    const int NC4 = 1440 / 4;  // 360
    const int idx = blockIdx.x * blockDim.x + threadIdx.x;
    if (idx >= BATCH * NC4) return;
    const int m   = idx / NC4;
    const int col = (idx - m * NC4) * 4;
    const int e   = col / 288;
    const int i   = col - e * 288;
    float4 v;
    if (i < 32) v = *(const float4*)(z + m * 32  + i);
    else        v = *(const float4*)(h + m * 256 + (i - 32));
    const float w = omega[m * NEXP + e];
    v.x *= w; v.y *= w; v.z *= w; v.w *= w;
    *(float4*)(out + (size_t)m * 1440 + col) = v;
}

// ---------------- gating layer 3 + softmax ----------------------------------
__global__ void gate3_softmax_k(const float* __restrict__ g2,
                                const float* __restrict__ gw3,
                                const float* __restrict__ gb3,
                                float* __restrict__ omega)
{
    const int warp = (blockIdx.x * blockDim.x + threadIdx.x) >> 5;
    const int lane = threadIdx.x & 31;
    if (warp >= BATCH) return;
    const float* row = g2 + warp * 128;
    float p[NEXP] = {0.f, 0.f, 0.f, 0.f, 0.f};
#pragma unroll
    for (int r = 0; r < 4; r++) {
        const int k = lane + r * 32;
        const float x = row[k];
#pragma unroll
        for (int e = 0; e < NEXP; e++) p[e] = fmaf(x, gw3[k * NEXP + e], p[e]);
    }
#pragma unroll
    for (int e = 0; e < NEXP; e++)
#pragma unroll
        for (int off = 16; off > 0; off >>= 1)
            p[e] += __shfl_xor_sync(0xffffffffu, p[e], off);
    if (lane == 0) {
        float mx = -1e30f;
#pragma unroll
        for (int e = 0; e < NEXP; e++) { p[e] += gb3[e]; mx = fmaxf(mx, p[e]); }
        float s = 0.f;
#pragma unroll
        for (int e = 0; e < NEXP; e++) { p[e] = expf(p[e] - mx); s += p[e]; }
        const float inv = 1.f / s;
#pragma unroll
        for (int e = 0; e < NEXP; e++) omega[warp * NEXP + e] = p[e] * inv;
    }
}

// ---------------- launcher ----------------------------------------------------
extern "C" void kernel_launch(void* const* d_in, const int* in_sizes, int n_in,
                              void* d_out, int out_size)
{
    const float* z      = (const float*)d_in[0];
    const float* p_prev = (const float*)d_in[1];
    const float* I      = (const float*)d_in[2];
    const float* gw1 = (const float*)d_in[3];  const float* gb1 = (const float*)d_in[4];
    const float* gw2 = (const float*)d_in[5];  const float* gb2 = (const float*)d_in[6];
    const float* gw3 = (const float*)d_in[7];  const float* gb3 = (const float*)d_in[8];
    const float* iw1 = (const float*)d_in[9];  const float* ib1 = (const float*)d_in[10];
    const float* iw2 = (const float*)d_in[11]; const float* ib2 = (const float*)d_in[12];
    const float* iw3 = (const float*)d_in[13]; const float* ib3 = (const float*)d_in[14];
    const float* wl1 = (const float*)d_in[15]; const float* bl1 = (const float*)d_in[16];
    const float* wl2 = (const float*)d_in[17]; const float* bl2 = (const float*)d_in[18];
    const float* wl3 = (const float*)d_in[19]; const float* bl3 = (const float*)d_in[20];
    float* out = (float*)d_out;

    float *bufA, *bufB, *g2, *omega, *h1, *h2, *a1, *a23;
    cudaGetSymbolAddress((void**)&bufA,  d_bufA);
    cudaGetSymbolAddress((void**)&bufB,  d_bufB);
    cudaGetSymbolAddress((void**)&g2,    d_g2);
    cudaGetSymbolAddress((void**)&omega, d_omega);
    cudaGetSymbolAddress((void**)&h1,    d_h1);
    cudaGetSymbolAddress((void**)&h2,    d_h2);
    cudaGetSymbolAddress((void**)&a1,    d_a1);
    cudaGetSymbolAddress((void**)&a23,   d_a23);

    auto kPlain  = mma_gemm<0, false, true>;
    auto kGate1  = mma_gemm<1, false, true>;
    auto kMoeElu = mma_gemm<0, true,  true>;
    auto kMoeOut = mma_gemm<0, true,  false>;
    const int SMEM = (2 * 4608 + 2 * 4224) * 4;  // 70656 B
    cudaFuncSetAttribute((const void*)kPlain,  cudaFuncAttributeMaxDynamicSharedMemorySize, SMEM);
    cudaFuncSetAttribute((const void*)kGate1,  cudaFuncAttributeMaxDynamicSharedMemorySize, SMEM);
    cudaFuncSetAttribute((const void*)kMoeElu, cudaFuncAttributeMaxDynamicSharedMemorySize, SMEM);
    cudaFuncSetAttribute((const void*)kMoeOut, cudaFuncAttributeMaxDynamicSharedMemorySize, SMEM);

    const dim3 blk(256);
    const dim3 gN256(2, BATCH / 128);
    const dim3 gN128(1, BATCH / 128);
    const dim3 gN524(5, BATCH / 128);

    // INet: 2048 -> 256 -> 256 -> 256 (ELU)
    kPlain<<<gN256, blk, SMEM>>>(I,    2048, nullptr, nullptr, nullptr, iw1, ib1, bufA, 256, 256, 2048);
    kPlain<<<gN256, blk, SMEM>>>(bufA,  256, nullptr, nullptr, nullptr, iw2, ib2, bufB, 256, 256,  256);
    kPlain<<<gN256, blk, SMEM>>>(bufB,  256, nullptr, nullptr, nullptr, iw3, ib3, bufA, 256, 256,  256);

    // gating: [z|p_prev] -> 256 -> 128 -> softmax(5)
    kGate1<<<gN256, blk, SMEM>>>(nullptr, 0, z, p_prev, nullptr, gw1, gb1, bufB, 256, 256, 556);
    kPlain<<<gN128, blk, SMEM>>>(bufB, 256, nullptr, nullptr, nullptr, gw2, gb2, g2, 128, 128, 256);
    gate3_softmax_k<<<BATCH / 8, blk>>>(g2, gw3, gb3, omega);

    // MoE layer 1: A' = omega-scaled [z|p|ienc], K=4060
    prep_moe1_k<<<(BATCH * 1015 + 255) / 256, blk>>>(z, p_prev, bufA, omega, a1);
    kMoeElu<<<gN256, blk, SMEM>>>(a1, 4060, nullptr, nullptr, omega, wl1, bl1, h1, 256, 256, 4060);

    // MoE layer 2: A' = omega-scaled [z|h1], K=1440
    prep_moe23_k<<<(BATCH * 360 + 255) / 256, blk>>>(z, h1, omega, a23);
    kMoeElu<<<gN256, blk, SMEM>>>(a23, 1440, nullptr, nullptr, omega, wl2, bl2, h2, 256, 256, 1440);

    // MoE layer 3: A' = omega-scaled [z|h2], K=1440, N=524, no ELU
    prep_moe23_k<<<(BATCH * 360 + 255) / 256, blk>>>(z, h2, omega, a23);
    kMoeOut<<<gN524, blk, SMEM>>>(a23, 1440, nullptr, nullptr, omega, wl3, bl3, out, 524, 524, 1440);
}